// round 3
// baseline (speedup 1.0000x reference)
#include <cuda_runtime.h>

#define NT     256
#define NBINS  10

__device__ float g_sum[NBINS];
__device__ float g_cnt[NBINS];

// Per-sample core. d = x_other - x_target, all MUFU-approx, branch-free.
//   u = e^d ; loss = log2(1+u)  (ln2 applied at finalize)
//   s = 20*sigmoid(d) = 20 - 20/(1+u) ; bin = trunc(s); bin in [0,9] <=> valid (g<1)
__device__ __forceinline__ void process(float dd, unsigned t, float* sum, float* cnt) {
    float d = __int_as_float(__float_as_int(dd) ^ (int)(t << 31));
    float z = d * 1.4426950408889634f;
    float u; asm("ex2.approx.f32 %0, %1;" : "=f"(u) : "f"(z));
    float v = 1.0f + u;
    float l; asm("lg2.approx.f32 %0, %1;" : "=f"(l) : "f"(v));
    float r; asm("rcp.approx.f32 %0, %1;" : "=f"(r) : "f"(v));
    float s = fmaf(-20.0f, r, 20.0f);
    int b = (int)s;                 // trunc; b in [0,9] only when valid
#pragma unroll
    for (int k = 0; k < NBINS; k++) {
        bool hit = (b == k);
        sum[k] += hit ? l : 0.0f;
        cnt[k] += hit ? 1.0f : 0.0f;
    }
}

// One "quad" = 4 samples: two float4 of outputs + one uint4 of int32 targets.
__global__ void __launch_bounds__(NT)
ghm_main(const float4* __restrict__ o4, const uint4* __restrict__ t4, int nquads) {
    __shared__ float s_red[2 * NBINS];
    const int tid = threadIdx.x;
    if (tid < 2 * NBINS) s_red[tid] = 0.0f;
    __syncthreads();

    float sum[NBINS], cnt[NBINS];
#pragma unroll
    for (int k = 0; k < NBINS; k++) { sum[k] = 0.0f; cnt[k] = 0.0f; }

    const int stride = gridDim.x * blockDim.x;
    int i = blockIdx.x * blockDim.x + tid;

    // 4x unrolled: 12 independent 16B loads batched up front (MLP=12)
    for (; i + 3 * stride < nquads; i += 4 * stride) {
        const int i0 = i, i1 = i + stride, i2 = i + 2 * stride, i3 = i + 3 * stride;
        float4 p0 = __ldcs(o4 + 2 * i0),     p1 = __ldcs(o4 + 2 * i1);
        float4 p2 = __ldcs(o4 + 2 * i2),     p3 = __ldcs(o4 + 2 * i3);
        float4 q0 = __ldcs(o4 + 2 * i0 + 1), q1 = __ldcs(o4 + 2 * i1 + 1);
        float4 q2 = __ldcs(o4 + 2 * i2 + 1), q3 = __ldcs(o4 + 2 * i3 + 1);
        uint4  t0 = __ldcs(t4 + i0), t1 = __ldcs(t4 + i1);
        uint4  t2 = __ldcs(t4 + i2), t3 = __ldcs(t4 + i3);

        process(p0.y - p0.x, t0.x, sum, cnt); process(p0.w - p0.z, t0.y, sum, cnt);
        process(q0.y - q0.x, t0.z, sum, cnt); process(q0.w - q0.z, t0.w, sum, cnt);
        process(p1.y - p1.x, t1.x, sum, cnt); process(p1.w - p1.z, t1.y, sum, cnt);
        process(q1.y - q1.x, t1.z, sum, cnt); process(q1.w - q1.z, t1.w, sum, cnt);
        process(p2.y - p2.x, t2.x, sum, cnt); process(p2.w - p2.z, t2.y, sum, cnt);
        process(q2.y - q2.x, t2.z, sum, cnt); process(q2.w - q2.z, t2.w, sum, cnt);
        process(p3.y - p3.x, t3.x, sum, cnt); process(p3.w - p3.z, t3.y, sum, cnt);
        process(q3.y - q3.x, t3.z, sum, cnt); process(q3.w - q3.z, t3.w, sum, cnt);
    }
    for (; i < nquads; i += stride) {
        float4 p = __ldcs(o4 + 2 * i);
        float4 q = __ldcs(o4 + 2 * i + 1);
        uint4  t = __ldcs(t4 + i);
        process(p.y - p.x, t.x, sum, cnt); process(p.w - p.z, t.y, sum, cnt);
        process(q.y - q.x, t.z, sum, cnt); process(q.w - q.z, t.w, sum, cnt);
    }

    // warp -> block -> global reduction
#pragma unroll
    for (int k = 0; k < NBINS; k++) {
#pragma unroll
        for (int off = 16; off > 0; off >>= 1) {
            sum[k] += __shfl_xor_sync(0xffffffffu, sum[k], off);
            cnt[k] += __shfl_xor_sync(0xffffffffu, cnt[k], off);
        }
    }
    if ((tid & 31) == 0) {
#pragma unroll
        for (int k = 0; k < NBINS; k++) {
            atomicAdd(&s_red[k],         sum[k]);
            atomicAdd(&s_red[NBINS + k], cnt[k]);
        }
    }
    __syncthreads();
    if (tid < NBINS) {
        atomicAdd(&g_sum[tid], s_red[tid]);
        atomicAdd(&g_cnt[tid], s_red[NBINS + tid]);
    }
}

__global__ void ghm_init() {
    if (threadIdx.x < NBINS) { g_sum[threadIdx.x] = 0.0f; g_cnt[threadIdx.x] = 0.0f; }
}

__global__ void ghm_finalize(const float* __restrict__ acc_sum, float* __restrict__ out) {
    if (threadIdx.x == 0) {
        float res = 0.0f;
#pragma unroll
        for (int b = 0; b < NBINS; b++) {
            float c = g_cnt[b];
            if (c > 0.0f) {
                float na = 0.75f * acc_sum[b] + 0.25f * c;
                res += g_sum[b] * 0.6931471805599453f / na;  // ln2: sums are log2-units
            }
        }
        out[0] = res;
    }
}

extern "C" void kernel_launch(void* const* d_in, const int* in_sizes, int n_in,
                              void* d_out, int out_size) {
    // Identify inputs BY SIZE (robust to ordering):
    //   outputs: largest (2N floats); acc_sum: 10 floats; targets: the remaining (N int32)
    int i_out = 0;
    for (int i = 1; i < n_in; i++) if (in_sizes[i] > in_sizes[i_out]) i_out = i;
    int i_acc = -1;
    for (int i = 0; i < n_in; i++) if (i != i_out && in_sizes[i] == NBINS) { i_acc = i; break; }
    if (i_acc < 0) {  // fallback: smallest non-outputs buffer
        for (int i = 0; i < n_in; i++)
            if (i != i_out && (i_acc < 0 || in_sizes[i] < in_sizes[i_acc])) i_acc = i;
    }
    int i_tgt = -1;
    for (int i = 0; i < n_in; i++) if (i != i_out && i != i_acc) { i_tgt = i; break; }

    const float4* o4  = (const float4*)d_in[i_out];
    const uint4*  t4  = (const uint4*)d_in[i_tgt];
    const float*  acc = (const float*)d_in[i_acc];
    const int n = in_sizes[i_tgt];        // number of samples (int32 targets)
    const int nquads = n / 4;             // 4 samples per uint4 of targets

    int sms = 148;
    cudaDeviceGetAttribute(&sms, cudaDevAttrMultiProcessorCount, 0);

    ghm_init<<<1, 32>>>();
    ghm_main<<<sms * 8, NT>>>(o4, t4, nquads);
    ghm_finalize<<<1, 32>>>(acc, (float*)d_out);
}